// round 13
// baseline (speedup 1.0000x reference)
#include <cuda_runtime.h>
#include <math.h>
#include <stdint.h>

#define BB 32
#define TT 200
#define EE 32
#define HH 128
#define VV 8000
#define MM (BB*TT)            // 6400
#define NT63 63               // 128-col B frag tiles
#define NT64 125              // 64-col gemm n-tiles (exact: 125*64=8000)
#define MT64 100              // 64-row A chunks
#define MT128 50              // 128-row gemm m-tiles

// Scratch (device globals)
__device__ float g_ux[MM*HH];              // [m][h]
__device__ float g_Afrag[MT64*8192];       // A fragments (64-row chunks), tf32
__device__ float g_Bfrag[NT63*16384];      // B fragments (128-col tiles), tf32

// ---------------------------------------------------------------------------
__device__ __forceinline__ float to_tf32(float x) {
    unsigned u;
    asm("cvt.rna.tf32.f32 %0, %1;" : "=r"(u) : "f"(x));
    return __uint_as_float(u);
}
__device__ __forceinline__ float tanh_fast(float x) {
    float r;
    asm("tanh.approx.f32 %0, %1;" : "=f"(r) : "f"(x));
    return r;
}
__device__ __forceinline__ void mma8(float c[4], const float4& a, float bx, float by) {
    asm("mma.sync.aligned.m16n8k8.row.col.f32.tf32.tf32.f32 "
        "{%0,%1,%2,%3},{%4,%5,%6,%7},{%8,%9},{%0,%1,%2,%3};"
        : "+f"(c[0]), "+f"(c[1]), "+f"(c[2]), "+f"(c[3])
        : "r"(__float_as_uint(a.x)), "r"(__float_as_uint(a.y)),
          "r"(__float_as_uint(a.z)), "r"(__float_as_uint(a.w)),
          "r"(__float_as_uint(bx)), "r"(__float_as_uint(by)));
}
__device__ __forceinline__ void cpa16(uint32_t s, const void* g) {
    asm volatile("cp.async.ca.shared.global [%0], [%1], 16;" :: "r"(s), "l"(g));
}

// ---------------------------------------------------------------------------
// ux[m][h] = sum_e x[m][e]*Uw[h][e] + Ub[h] + Wb[h]  [verified]
// ---------------------------------------------------------------------------
__global__ void k_ux(const float* __restrict__ x, const float* __restrict__ Uw,
                     const float* __restrict__ Ub, const float* __restrict__ Wb) {
    __shared__ float UwT[EE][HH];
    __shared__ float xs[32][EE];
    __shared__ float bias[HH];
    int tid = threadIdx.x;

    for (int f = tid; f < HH * EE / 4; f += 256) {
        int h = f / (EE / 4), c = f % (EE / 4);
        float4 u = ((const float4*)Uw)[f];
        UwT[c * 4 + 0][h] = u.x;
        UwT[c * 4 + 1][h] = u.y;
        UwT[c * 4 + 2][h] = u.z;
        UwT[c * 4 + 3][h] = u.w;
    }
    if (tid < HH) bias[tid] = Ub[tid] + Wb[tid];
    int m0 = blockIdx.x * 32;
    {
        int r = tid / 8, c = tid % 8;
        ((float4*)&xs[r][0])[c] = ((const float4*)x)[(size_t)(m0 + r) * (EE / 4) + c];
    }
    __syncthreads();
    int h = tid % HH;
    int half = tid / HH;
    #pragma unroll
    for (int rr = 0; rr < 16; rr++) {
        int r = half * 16 + rr;
        float acc = bias[h];
        const float4* xv = (const float4*)&xs[r][0];
        #pragma unroll
        for (int e4 = 0; e4 < EE / 4; e4++) {
            float4 xf = xv[e4];
            acc += UwT[e4 * 4 + 0][h] * xf.x;
            acc += UwT[e4 * 4 + 1][h] * xf.y;
            acc += UwT[e4 * 4 + 2][h] * xf.z;
            acc += UwT[e4 * 4 + 3][h] * xf.w;
        }
        g_ux[(size_t)(m0 + r) * HH + h] = acc;
    }
}

// ---------------------------------------------------------------------------
// Combined: blocks 0..31 = recurrence with cp.async-staged ux chunks;
//           blocks 32..94 = prepB tiles (verified formulas).
// ---------------------------------------------------------------------------
#define CHK 40    // steps per ux chunk (5 chunks)

__global__ void __launch_bounds__(256, 1)
k_rnnprep(const float* __restrict__ Ww, const float* __restrict__ Vw,
          float* __restrict__ out_hidden) {
    extern __shared__ float dynsm[];
    int tid = threadIdx.x;

    if (blockIdx.x >= BB) {
        // ---- prepB [verified] ----
        float* Bs = dynsm;                   // 16384 floats
        int nt = blockIdx.x - BB;
        int n0 = nt * 128;
        #pragma unroll
        for (int i = 0; i < 16; i++) {
            int f  = tid + i * 256;
            int nn = f >> 5;
            int c4 = f & 31;
            int gn = n0 + nn;
            float4 v = (gn < VV) ? ((const float4*)Vw)[(size_t)gn * 32 + c4]
                                 : make_float4(0.f, 0.f, 0.f, 0.f);
            int k0 = c4 * 4;
            int kg = k0 >> 3, ip = nn >> 4;
            int reg  = ((nn >> 3) & 1) * 2 + ((k0 & 7) >> 2);
            int base = (kg * 8 + ip) * 128 + ((nn & 7) << 2) * 4 + reg;
            Bs[base + 0]  = to_tf32(v.x);
            Bs[base + 4]  = to_tf32(v.y);
            Bs[base + 8]  = to_tf32(v.z);
            Bs[base + 12] = to_tf32(v.w);
        }
        __syncthreads();
        float4* dst = (float4*)g_Bfrag + (size_t)nt * 4096;
        #pragma unroll
        for (int i = 0; i < 16; i++)
            dst[tid + i * 256] = ((float4*)Bs)[tid + i * 256];
        return;
    }

    // ---- recurrence ----
    // dynsm layout: uxs[2][CHK*HH] (10240 floats), hb[2][HH] (256 floats)
    float* uxs = dynsm;
    float* hb  = dynsm + 2 * CHK * HH;
    uint32_t s_ux = (uint32_t)__cvta_generic_to_shared(uxs);

    int j    = tid >> 1;
    int half = tid & 1;
    int b    = blockIdx.x;

    float4 w[16];
    const float4* Ww4 = (const float4*)Ww;
    #pragma unroll
    for (int i = 0; i < 16; i++)
        w[i] = Ww4[(size_t)j * 32 + half * 16 + i];

    if (half == 0) hb[j] = 0.0f;

    const float* uxb = g_ux + (size_t)b * TT * HH;

    // load chunk 0 (CHK*HH floats = 1280 float4, 5 per thread)
    #pragma unroll
    for (int i = 0; i < 5; i++)
        cpa16(s_ux + (tid + i * 256) * 16, (const float4*)uxb + tid + i * 256);
    asm volatile("cp.async.commit_group;");

    // A-frag index pieces depending only on j (k = j) [verified]
    int kg = j >> 3, kl = j & 7;
    int kcol = (kl & 3) * 4 + 2 * (kl >> 2);

    int p = 0;
    float v = 0.0f;
    for (int c = 0; c < TT / CHK; c++) {
        if (c + 1 < TT / CHK) {
            const float4* src = (const float4*)(uxb + (size_t)(c + 1) * CHK * HH);
            uint32_t dst = s_ux + (((c + 1) & 1) * CHK * HH) * 4;
            #pragma unroll
            for (int i = 0; i < 5; i++)
                cpa16(dst + (tid + i * 256) * 16, src + tid + i * 256);
            asm volatile("cp.async.commit_group;");
            asm volatile("cp.async.wait_group 1;");
        } else {
            asm volatile("cp.async.wait_group 0;");
        }
        __syncthreads();   // chunk c visible to all; also covers hb init (c=0)

        float* uxc = uxs + (c & 1) * CHK * HH;
        for (int tt = 0; tt < CHK; tt++) {
            float uxr = uxc[tt * HH + j];   // LDS, issued early
            const float4* h4 = (const float4*)(hb + p * HH) + half * 16;
            float a = 0.f, b2 = 0.f, cc = 0.f, d = 0.f;
            #pragma unroll
            for (int i = 0; i < 16; i++) {
                float4 hv = h4[i];
                a  += w[i].x * hv.x;
                b2 += w[i].y * hv.y;
                cc += w[i].z * hv.z;
                d  += w[i].w * hv.w;
            }
            float acc = (a + b2) + (cc + d);
            acc += __shfl_xor_sync(0xFFFFFFFFu, acc, 1);
            v = tanh_fast(acc + uxr);
            if (half == 0) {
                hb[(1 - p) * HH + j] = v;
                int m  = b * TT + c * CHK + tt;
                int mt = m >> 6, mr = m & 63;
                int im = mr >> 4, r = mr & 15;
                int idx = mt * 8192 + (kg * 4 + im) * 128
                        + ((r & 7) << 4) + kcol + (r >> 3);
                g_Afrag[idx] = to_tf32(v);
            }
            __syncthreads();
            p ^= 1;
        }
    }
    if (half == 0) out_hidden[b * HH + j] = v;
}

// ---------------------------------------------------------------------------
// Output GEMM: BM=128, BN=64, occ 4, mma loop identical to R12 (verified).
// Epilogue: SMEM-staged (64x68 pad) -> coalesced STG.128 in 2 passes.
// SMEM: B 32KB + stage 17KB = 49KB.
// ---------------------------------------------------------------------------
__global__ void __launch_bounds__(256, 4)
k_gemm(const float* __restrict__ Vb, float* __restrict__ out) {
    extern __shared__ float smf[];
    float4* Bs4 = (float4*)smf;           // 2048 float4 (32 KB)
    float*  stg = smf + 8192;             // 64*68 floats (17 KB)

    int tid  = threadIdx.x;
    __builtin_assume(tid >= 0 && tid < 256);
    int warp = tid >> 5;
    int lane = tid & 31;
    int nt = blockIdx.x;                  // 0..124
    int mt = blockIdx.y;                  // 0..49

    // B: 4-ip slice of 128-col frag tile nt>>1  [R12 verified]
    const float4* Bsrc = (const float4*)g_Bfrag + (size_t)(nt >> 1) * 4096
                       + (size_t)(nt & 1) * 4 * 32;
    uint32_t sB = (uint32_t)__cvta_generic_to_shared(Bs4);
    #pragma unroll
    for (int i = 0; i < 8; i++) {
        int f = tid + i * 256;
        int kg = f >> 7, ipl = (f >> 5) & 3, l = f & 31;
        cpa16(sB + f * 16, Bsrc + (kg * 8 + ipl) * 32 + l);
    }
    asm volatile("cp.async.commit_group;");

    int wm = warp >> 1;   // 0..3 (32-row group)
    int wn = warp & 1;    // 0..1 (32-col group)

    const float4* Aw = (const float4*)g_Afrag + (size_t)(2 * mt + (wm >> 1)) * 2048
                     + ((wm & 1) * 2) * 32 + lane;

    float c[2][4][4];
    #pragma unroll
    for (int a = 0; a < 2; a++)
        #pragma unroll
        for (int b = 0; b < 4; b++)
            #pragma unroll
            for (int d = 0; d < 4; d++) c[a][b][d] = 0.0f;

    float4 a_cur[2], a_nxt[2];
    a_cur[0] = Aw[0];
    a_cur[1] = Aw[32];

    asm volatile("cp.async.wait_group 0;");
    __syncthreads();

    #pragma unroll
    for (int kg = 0; kg < 16; kg++) {
        if (kg < 15) {
            a_nxt[0] = Aw[(kg + 1) * 128];
            a_nxt[1] = Aw[(kg + 1) * 128 + 32];
        }
        float4 b0 = Bs4[(kg * 4 + wn * 2 + 0) * 32 + lane];
        float4 b1 = Bs4[(kg * 4 + wn * 2 + 1) * 32 + lane];
        #pragma unroll
        for (int im = 0; im < 2; im++) {
            mma8(c[im][0], a_cur[im], b0.x, b0.y);
            mma8(c[im][1], a_cur[im], b0.z, b0.w);
            mma8(c[im][2], a_cur[im], b1.x, b1.y);
            mma8(c[im][3], a_cur[im], b1.z, b1.w);
        }
        a_cur[0] = a_nxt[0];
        a_cur[1] = a_nxt[1];
    }

    // ---- staged epilogue: 2 passes of 64 rows ----
    int m0 = mt * 128, n0 = nt * 64;
    #pragma unroll
    for (int pass = 0; pass < 2; pass++) {
        __syncthreads();
        if ((wm >> 1) == pass) {
            int rbase = (wm & 1) * 32;
            #pragma unroll
            for (int nt4 = 0; nt4 < 4; nt4++) {
                int cl = wn * 32 + nt4 * 8 + (lane & 3) * 2;
                float vbx = Vb[n0 + cl], vby = Vb[n0 + cl + 1];
                #pragma unroll
                for (int im = 0; im < 2; im++) {
                    int rl = rbase + im * 16 + (lane >> 2);
                    float2 o0 = make_float2(c[im][nt4][0] + vbx, c[im][nt4][1] + vby);
                    float2 o1 = make_float2(c[im][nt4][2] + vbx, c[im][nt4][3] + vby);
                    *(float2*)&stg[rl * 68 + cl] = o0;
                    *(float2*)&stg[(rl + 8) * 68 + cl] = o1;
                }
            }
        }
        __syncthreads();
        #pragma unroll
        for (int i = 0; i < 4; i++) {
            int f = tid + i * 256;          // 0..1023
            int r = f >> 4, c4 = f & 15;
            float4 v = *(float4*)&stg[r * 68 + c4 * 4];
            *(float4*)(out + (size_t)(m0 + pass * 64 + r) * VV + n0 + c4 * 4) = v;
        }
    }
}

// ---------------------------------------------------------------------------
extern "C" void kernel_launch(void* const* d_in, const int* in_sizes, int n_in,
                              void* d_out, int out_size) {
    const float* x  = (const float*)d_in[0];
    const float* Ww = (const float*)d_in[1];
    const float* Wb = (const float*)d_in[2];
    const float* Uw = (const float*)d_in[3];
    const float* Ub = (const float*)d_in[4];
    const float* Vw = (const float*)d_in[5];
    const float* Vb = (const float*)d_in[6];
    float* out = (float*)d_out;

    cudaFuncSetAttribute(k_rnnprep, cudaFuncAttributeMaxDynamicSharedMemorySize, 65536);
    cudaFuncSetAttribute(k_gemm,    cudaFuncAttributeMaxDynamicSharedMemorySize,
                         (8192 + 64 * 68) * 4);

    k_ux<<<MM / 32, 256>>>(x, Uw, Ub, Wb);
    k_rnnprep<<<BB + NT63, 256, 65536>>>(Ww, Vw, out + (size_t)MM * VV);
    k_gemm<<<dim3(NT64, MT128), 256, (8192 + 64 * 68) * 4>>>(Vb, out);
}